// round 16
// baseline (speedup 1.0000x reference)
#include <cuda_runtime.h>

// x1:   (16, 1, 224, 224) fp32
// W:    (288, 1, 3, 3)    fp32
// bias: (1, 288, 222, 222) fp32
// out:  (16, 288, 222, 222) fp32 = relu(conv_valid(x1, W) + bias)

#define B_      16
#define COUT_   288
#define HIN_    224
#define WIN_    224
#define HOUT_   222
#define WOUT_   222
#define PLANE_  (HOUT_ * WOUT_)     // 49284
#define BSTRIDE (COUT_ * PLANE_)    // 14193792 elems per batch
#define ROWS_CTA 1                  // 1 output row per CTA (222 groups)
#define IROWS   (ROWS_CTA + 2)      // 3 input rows
#define NBATCH  4                   // batches per CTA (bias loaded once for 4)
#define NPAIR   111                 // float2 pixel pairs per row

__global__ __launch_bounds__(128, 6) void conv_bias_relu_kernel(
    const float* __restrict__ x,
    const float* __restrict__ Wt,
    const float* __restrict__ bias,
    float* __restrict__ out)
{
    // Weights padded to 12 floats/channel: 2x LDS.128 + 1x LDS.32 per channel.
    __shared__ __align__(16) float sW[COUT_ * 12];            // 13824 B
    __shared__ __align__(8)  float sIn[NBATCH][IROWS][WIN_];  // 10752 B

    const int h  = blockIdx.x;            // 0..221 (output row)
    const int bg = blockIdx.y;            // 0..3   (batch quad)
    const int t  = threadIdx.x;           // 0..127
    const int b0 = bg * NBATCH;

    // Cooperative weight load with 9->12 padding.
    for (int i = t; i < COUT_ * 9; i += 128) {
        int c = i / 9, j = i - c * 9;
        sW[c * 12 + j] = Wt[i];
    }

    // Cooperative load: 4 batches x 3 input rows x 224 cols.
    for (int i = t; i < NBATCH * IROWS * WIN_; i += 128) {
        int bb = i / (IROWS * WIN_);
        int rem = i - bb * (IROWS * WIN_);
        int r = rem / WIN_, w = rem - r * WIN_;
        sIn[bb][r][w] = x[(b0 + bb) * (HIN_ * WIN_) + (h + r) * WIN_ + w];
    }

    __syncthreads();

    if (t >= NPAIR) return;   // 111 active pair-threads

    // Taps: 4 batches x 3 rows x 4 consecutive cols (2t..2t+3). 48 registers.
    float tap[NBATCH][IROWS][4];
    #pragma unroll
    for (int bb = 0; bb < NBATCH; bb++) {
        #pragma unroll
        for (int r = 0; r < IROWS; r++) {
            float2 a = *reinterpret_cast<const float2*>(&sIn[bb][r][2 * t]);
            float2 c = *reinterpret_cast<const float2*>(&sIn[bb][r][2 * t + 2]);
            tap[bb][r][0] = a.x; tap[bb][r][1] = a.y;
            tap[bb][r][2] = c.x; tap[bb][r][3] = c.y;
        }
    }

    // 32-bit element offsets (whole out tensor = 227M elems; per-quad base
    // b0*BSTRIDE + channel offsets stay < 2^31 bytes from `out`).
    const int ofs = h * WOUT_ + 2 * t;                 // 8B aligned
    const float* bp = bias + ofs;
    float*       op = out + (size_t)b0 * BSTRIDE + ofs;

    #pragma unroll 2
    for (int c = 0; c < COUT_; c++) {
        const float4 wA = *reinterpret_cast<const float4*>(&sW[c * 12]);     // w0..w3
        const float4 wB = *reinterpret_cast<const float4*>(&sW[c * 12 + 4]); // w4..w7
        const float  w8 = sW[c * 12 + 8];

        // Bias loaded ONCE per channel, reused for all 4 batches.
        const float2 bv = __ldg(reinterpret_cast<const float2*>(bp));

        #pragma unroll
        for (int bb = 0; bb < NBATCH; bb++) {
            float y0, y1;
            y0 = tap[bb][0][0] * wA.x;             y1 = tap[bb][0][1] * wA.x;
            y0 = fmaf(tap[bb][0][1], wA.y, y0);    y1 = fmaf(tap[bb][0][2], wA.y, y1);
            y0 = fmaf(tap[bb][0][2], wA.z, y0);    y1 = fmaf(tap[bb][0][3], wA.z, y1);
            y0 = fmaf(tap[bb][1][0], wA.w, y0);    y1 = fmaf(tap[bb][1][1], wA.w, y1);
            y0 = fmaf(tap[bb][1][1], wB.x, y0);    y1 = fmaf(tap[bb][1][2], wB.x, y1);
            y0 = fmaf(tap[bb][1][2], wB.y, y0);    y1 = fmaf(tap[bb][1][3], wB.y, y1);
            y0 = fmaf(tap[bb][2][0], wB.z, y0);    y1 = fmaf(tap[bb][2][1], wB.z, y1);
            y0 = fmaf(tap[bb][2][1], wB.w, y0);    y1 = fmaf(tap[bb][2][2], wB.w, y1);
            y0 = fmaf(tap[bb][2][2], w8,  y0);     y1 = fmaf(tap[bb][2][3], w8,  y1);

            float2 o;
            o.x = fmaxf(y0 + bv.x, 0.0f);
            o.y = fmaxf(y1 + bv.y, 0.0f);
            *reinterpret_cast<float2*>(op + (size_t)bb * BSTRIDE) = o;
        }
        bp += PLANE_;
        op += PLANE_;
    }
}

extern "C" void kernel_launch(void* const* d_in, const int* in_sizes, int n_in,
                              void* d_out, int out_size)
{
    const float* x    = (const float*)d_in[0];
    const float* Wt   = (const float*)d_in[1];
    const float* bias = (const float*)d_in[2];
    float*       out  = (float*)d_out;

    dim3 grid(HOUT_, B_ / NBATCH);   // 222 x 4 = 888 CTAs = 148 SMs x 6 (one wave)
    dim3 block(128);                 // 4 warps, 111 active pair-threads
    conv_bias_relu_kernel<<<grid, block>>>(x, Wt, bias, out);
}

// round 17
// speedup vs baseline: 1.0459x; 1.0459x over previous
#include <cuda_runtime.h>

// x1:   (16, 1, 224, 224) fp32
// W:    (288, 1, 3, 3)    fp32
// bias: (1, 288, 222, 222) fp32
// out:  (16, 288, 222, 222) fp32 = relu(conv_valid(x1, W) + bias)

#define B_      16
#define COUT_   288
#define HIN_    224
#define WIN_    224
#define HOUT_   222
#define WOUT_   222
#define PLANE_  (HOUT_ * WOUT_)     // 49284
#define BSTRIDE (COUT_ * PLANE_)    // elems per batch
#define ROWS_CTA 3                  // 3 output rows per CTA (222 = 74*3)
#define IROWS   (ROWS_CTA + 2)      // 5 input rows
#define NBATCH  2                   // batches per CTA (bias reused in registers)
#define NPAIR   111                 // float2 pixel pairs per row

__global__ __launch_bounds__(128, 4) void conv_bias_relu_kernel(
    const float* __restrict__ x,
    const float* __restrict__ Wt,
    const float* __restrict__ bias,
    float* __restrict__ out)
{
    // Weights padded to 12 floats/channel: 2x LDS.128 + 1x LDS.32 per channel.
    __shared__ __align__(16) float sW[COUT_ * 12];            // 13824 B
    __shared__ __align__(8)  float sIn[NBATCH][IROWS][WIN_];  //  8960 B

    const int hg = blockIdx.x;            // 0..73  (row group)
    const int bg = blockIdx.y;            // 0..7   (batch pair)
    const int t  = threadIdx.x;           // 0..127
    const int h0 = hg * ROWS_CTA;
    const int b0 = bg * NBATCH;

    // Cooperative weight load with 9->12 padding.
    for (int i = t; i < COUT_ * 9; i += 128) {
        int c = i / 9, j = i - c * 9;
        sW[c * 12 + j] = Wt[i];
    }

    // Cooperative load: 2 batches x 5 input rows x 224 cols.
    for (int i = t; i < NBATCH * IROWS * WIN_; i += 128) {
        int bb = i / (IROWS * WIN_);
        int rem = i - bb * (IROWS * WIN_);
        int r = rem / WIN_, w = rem - r * WIN_;
        sIn[bb][r][w] = x[(b0 + bb) * (HIN_ * WIN_) + (h0 + r) * WIN_ + w];
    }

    __syncthreads();

    if (t >= NPAIR) return;   // 111 active pair-threads

    // Taps: 2 batches x 5 rows x 4 consecutive cols (2t..2t+3). 40 registers.
    float tap[NBATCH][IROWS][4];
    #pragma unroll
    for (int bb = 0; bb < NBATCH; bb++) {
        #pragma unroll
        for (int r = 0; r < IROWS; r++) {
            float2 a = *reinterpret_cast<const float2*>(&sIn[bb][r][2 * t]);
            float2 c = *reinterpret_cast<const float2*>(&sIn[bb][r][2 * t + 2]);
            tap[bb][r][0] = a.x; tap[bb][r][1] = a.y;
            tap[bb][r][2] = c.x; tap[bb][r][3] = c.y;
        }
    }

    const int ofs = h0 * WOUT_ + 2 * t;                 // 8B aligned
    const float* bp  = bias + ofs;
    float*       op0 = out + (size_t)(b0    ) * BSTRIDE + ofs;
    float*       op1 = out + (size_t)(b0 + 1) * BSTRIDE + ofs;

    #pragma unroll 2
    for (int c = 0; c < COUT_; c++) {
        const float4 wA = *reinterpret_cast<const float4*>(&sW[c * 12]);     // w0..w3
        const float4 wB = *reinterpret_cast<const float4*>(&sW[c * 12 + 4]); // w4..w7
        const float  w8 = sW[c * 12 + 8];

        // Bias loaded ONCE per channel, reused for both batches.
        float2 bv[ROWS_CTA];
        #pragma unroll
        for (int r = 0; r < ROWS_CTA; r++)
            bv[r] = __ldg(reinterpret_cast<const float2*>(bp + r * WOUT_));

        #pragma unroll
        for (int bb = 0; bb < NBATCH; bb++) {
            float* op = bb ? op1 : op0;
            #pragma unroll
            for (int r = 0; r < ROWS_CTA; r++) {
                float y0, y1;
                y0 = tap[bb][r][0] * wA.x;              y1 = tap[bb][r][1] * wA.x;
                y0 = fmaf(tap[bb][r][1],   wA.y, y0);   y1 = fmaf(tap[bb][r][2],   wA.y, y1);
                y0 = fmaf(tap[bb][r][2],   wA.z, y0);   y1 = fmaf(tap[bb][r][3],   wA.z, y1);
                y0 = fmaf(tap[bb][r+1][0], wA.w, y0);   y1 = fmaf(tap[bb][r+1][1], wA.w, y1);
                y0 = fmaf(tap[bb][r+1][1], wB.x, y0);   y1 = fmaf(tap[bb][r+1][2], wB.x, y1);
                y0 = fmaf(tap[bb][r+1][2], wB.y, y0);   y1 = fmaf(tap[bb][r+1][3], wB.y, y1);
                y0 = fmaf(tap[bb][r+2][0], wB.z, y0);   y1 = fmaf(tap[bb][r+2][1], wB.z, y1);
                y0 = fmaf(tap[bb][r+2][1], wB.w, y0);   y1 = fmaf(tap[bb][r+2][2], wB.w, y1);
                y0 = fmaf(tap[bb][r+2][2], w8,   y0);   y1 = fmaf(tap[bb][r+2][3], w8,   y1);

                float2 o;
                o.x = fmaxf(y0 + bv[r].x, 0.0f);
                o.y = fmaxf(y1 + bv[r].y, 0.0f);
                *reinterpret_cast<float2*>(op + r * WOUT_) = o;
            }
        }
        bp  += PLANE_;
        op0 += PLANE_;
        op1 += PLANE_;
    }
}

extern "C" void kernel_launch(void* const* d_in, const int* in_sizes, int n_in,
                              void* d_out, int out_size)
{
    const float* x    = (const float*)d_in[0];
    const float* Wt   = (const float*)d_in[1];
    const float* bias = (const float*)d_in[2];
    float*       out  = (float*)d_out;

    dim3 grid(HOUT_ / ROWS_CTA, B_ / NBATCH);   // 74 x 8 = 592 CTAs = 4/SM, one wave
    dim3 block(128);                            // 4 warps, 111 active pair-threads
    conv_bias_relu_kernel<<<grid, block>>>(x, Wt, bias, out);
}